// round 2
// baseline (speedup 1.0000x reference)
#include <cuda_runtime.h>
#include <math.h>

#define KHALF 5
#define KW 11
#define MAXB 16
#define MAXT 2048
#define MAXD 512
#define MAXL 160
#define THRESH 0.9f

// ---- device scratch (no allocations allowed) ----
__device__ float d_weff[KW * MAXD + 1];          // folded conv*proj weights + bias at [KW*D]
__device__ float d_g[MAXB * MAXT * KW];          // per-(b,t) dot with each of 11 taps
__device__ float d_scale[MAXB];                  // ylens[b] / rowsum(alpha[b])
__device__ int   d_tfire[MAXB * MAXL];           // fire time of slot l for batch b
__device__ int   d_nfinal[MAXB];                 // number of fired tokens per batch

// ---------------------------------------------------------------------------
// Zero the whole output buffer (it is poisoned to 0xAA).
__global__ void k_memset0(float* p, int n) {
    int i = blockIdx.x * blockDim.x + threadIdx.x;
    int stride = gridDim.x * blockDim.x;
    int n4 = n >> 2;
    float4 z = make_float4(0.f, 0.f, 0.f, 0.f);
    float4* p4 = (float4*)p;
    for (int j = i; j < n4; j += stride) p4[j] = z;
    // tail
    for (int j = n4 * 4 + i; j < n; j += stride) p[j] = 0.f;
}

// ---------------------------------------------------------------------------
// w_eff[k*D+d] = sum_c conv_w[(k*D+d)*C + c] * proj_w[c]
// w_eff[KW*D]  = sum_c conv_b[c]*proj_w[c] + proj_b[0]   (bias)
// One warp per output element.
__global__ void k_weff(const float* __restrict__ cw, const float* __restrict__ cb,
                       const float* __restrict__ pw, const float* __restrict__ pb,
                       int D, int C) {
    int wid  = (blockIdx.x * blockDim.x + threadIdx.x) >> 5;
    int lane = threadIdx.x & 31;
    int NE = KW * D;
    if (wid > NE) return;
    float s = 0.f;
    if (wid == NE) {
        for (int c = lane; c < C; c += 32) s += cb[c] * pw[c];
    } else {
        const float* row = cw + (size_t)wid * C;
        for (int c = lane; c < C; c += 32) s += row[c] * pw[c];
    }
#pragma unroll
    for (int o = 16; o > 0; o >>= 1) s += __shfl_xor_sync(0xffffffffu, s, o);
    if (lane == 0) d_weff[wid] = (wid == NE) ? (s + pb[0]) : s;
}

// ---------------------------------------------------------------------------
// g[(b*T+t)*KW + k] = dot(eouts[b,t,:], w_eff[k,:])  — one warp per (b,t) row,
// eouts read exactly once, w_eff cached in smem. Assumes D == 512.
__global__ void k_g(const float* __restrict__ e, int BT, int D) {
    __shared__ float4 sw[KW * MAXD / 4];
    int tid = threadIdx.x;
    {
        float* swf = (float*)sw;
        for (int i = tid; i < KW * D; i += blockDim.x) swf[i] = d_weff[i];
    }
    __syncthreads();
    int gw = blockIdx.x * (blockDim.x >> 5) + (tid >> 5);
    int lane = tid & 31;
    if (gw >= BT) return;

    const float4* erow = (const float4*)(e + (size_t)gw * D);
    float4 ev[4];
#pragma unroll
    for (int jj = 0; jj < 4; jj++) ev[jj] = erow[lane + 32 * jj];

    float acc[KW];
#pragma unroll
    for (int k = 0; k < KW; k++) {
        float a = 0.f;
#pragma unroll
        for (int jj = 0; jj < 4; jj++) {
            float4 w4 = sw[k * (MAXD / 4) + lane + 32 * jj];
            a += ev[jj].x * w4.x + ev[jj].y * w4.y + ev[jj].z * w4.z + ev[jj].w * w4.w;
        }
        acc[k] = a;
    }
#pragma unroll
    for (int k = 0; k < KW; k++) {
#pragma unroll
        for (int o = 16; o > 0; o >>= 1)
            acc[k] += __shfl_xor_sync(0xffffffffu, acc[k], o);
    }
    float* gout = d_g + (size_t)gw * KW;
#pragma unroll
    for (int k = 0; k < KW; k++)
        if (lane == k) gout[k] = acc[k];
}

// ---------------------------------------------------------------------------
// alpha[b,t] = sigmoid( sum_k g[b, t+k-5, k] + bias ); also rowsum -> scale[b].
__global__ void k_alpha(float* __restrict__ alpha_out, const int* __restrict__ ylens,
                        int T, int D) {
    __shared__ float red[256];
    int b = blockIdx.x;
    float bias = d_weff[KW * D];
    float lsum = 0.f;
    const float* gb = d_g + (size_t)b * T * KW;
    for (int t = threadIdx.x; t < T; t += blockDim.x) {
        float x = bias;
#pragma unroll
        for (int k = 0; k < KW; k++) {
            int tt = t + k - KHALF;
            if (tt >= 0 && tt < T) x += gb[tt * KW + k];
        }
        float a = 1.0f / (1.0f + expf(-x));
        alpha_out[(size_t)b * T + t] = a;
        lsum += a;
    }
    red[threadIdx.x] = lsum;
    __syncthreads();
    for (int s = 128; s > 0; s >>= 1) {
        if (threadIdx.x < s) red[threadIdx.x] += red[threadIdx.x + s];
        __syncthreads();
    }
    if (threadIdx.x == 0) d_scale[b] = (float)ylens[b] / red[0];
}

// ---------------------------------------------------------------------------
// Per-batch serial integrate-and-fire scan (thread 0 of each block), then
// parallel scatter of the sparse attention weights into aws.
__global__ void k_scan(const float* __restrict__ alpha_out, float* __restrict__ aws,
                       const int* __restrict__ elens, const int* __restrict__ ylens,
                       int T, int Lp1) {
    __shared__ float sa[MAXT];
    __shared__ float sw1[MAXT];
    __shared__ float sw2[MAXT];
    __shared__ short sslot[MAXT];
    __shared__ unsigned char sflag[MAXT];

    int b = blockIdx.x;
    float sc = d_scale[b];
    for (int t = threadIdx.x; t < T; t += blockDim.x)
        sa[t] = alpha_out[(size_t)b * T + t] * sc;
    __syncthreads();

    if (threadIdx.x == 0) {
        float acc = 0.f;
        int ntok = 0;
        int el = elens[b], yl = ylens[b];
#pragma unroll 4
        for (int t = 0; t < T; t++) {
            float a = sa[t];
            acc += a;                       // unconditional in reference
            bool active = (t < el) && (ntok < yl);
            if (active && acc >= THRESH) {
                float ak1 = 1.0f - acc;
                float ak2 = a - ak1;
                sw1[t] = ak1; sw2[t] = ak2;
                sslot[t] = (short)ntok; sflag[t] = 2;
                d_tfire[b * MAXL + ntok] = t;
                ntok++;
                acc = ak2;
            } else if (active) {
                sw1[t] = a; sslot[t] = (short)ntok; sflag[t] = 1;
            } else {
                sflag[t] = 0;
            }
        }
        d_nfinal[b] = ntok;
    }
    __syncthreads();

    float* awb = aws + (size_t)b * Lp1 * T;
    for (int t = threadIdx.x; t < T; t += blockDim.x) {
        int f = sflag[t];
        if (f) {
            int s = sslot[t];
            awb[(size_t)s * T + t] = sw1[t];
            if (f == 2) awb[(size_t)(s + 1) * T + t] = sw2[t];
        }
    }
}

// ---------------------------------------------------------------------------
// fired[b,l,:] = sum_{t=tlo..thi} aws[b,l,t] * eouts[b,t,:]
// One block per (l,b); contiguous t-range bounded by fire times. D==512, 128 thr.
__global__ void k_fired(const float* __restrict__ e, const float* __restrict__ aws,
                        float* __restrict__ fired, int T, int D, int L) {
    int b = blockIdx.y, l = blockIdx.x;
    if (l >= d_nfinal[b]) return;   // unfired slots remain zero (memset)
    int tlo = (l == 0) ? 0 : d_tfire[b * MAXL + l - 1];
    int thi = d_tfire[b * MAXL + l];
    const float* awr = aws + ((size_t)b * (L + 1) + l) * T;
    const float4* eb = (const float4*)(e + (size_t)b * T * D);
    int d4 = threadIdx.x;           // 0..127 covers D=512 as float4
    float4 acc = make_float4(0.f, 0.f, 0.f, 0.f);
    for (int t = tlo; t <= thi; t++) {
        float w = awr[t];
        float4 ev = eb[(size_t)t * (D / 4) + d4];
        acc.x += w * ev.x; acc.y += w * ev.y;
        acc.z += w * ev.z; acc.w += w * ev.w;
    }
    ((float4*)(fired + ((size_t)b * L + l) * D))[d4] = acc;
}

// ---------------------------------------------------------------------------
extern "C" void kernel_launch(void* const* d_in, const int* in_sizes, int n_in,
                              void* d_out, int out_size) {
    const float* eouts  = (const float*)d_in[0];
    const float* conv_w = (const float*)d_in[1];
    const float* conv_b = (const float*)d_in[2];
    const float* proj_w = (const float*)d_in[3];
    const float* proj_b = (const float*)d_in[4];
    const int*   elens  = (const int*)d_in[5];
    const int*   ylens  = (const int*)d_in[6];

    int B = in_sizes[5];                    // elens element count
    int C = in_sizes[2];                    // conv_b
    int D = in_sizes[1] / (KW * C);         // conv_w = [KW, D, C]
    int T = in_sizes[0] / (B * D);          // eouts = [B, T, D]
    // out = B*L*D (fired) + B*T (alpha) + B*(L+1)*T (aws)
    int L = (out_size - 2 * B * T) / (B * (D + T));

    float* fired   = (float*)d_out;
    float* alpha_o = fired + (size_t)B * L * D;
    float* aws     = alpha_o + (size_t)B * T;

    k_memset0<<<1024, 256>>>((float*)d_out, out_size);
    k_weff<<<(KW * D + 1 + 7) / 8, 256>>>(conv_w, conv_b, proj_w, proj_b, D, C);
    k_g<<<(B * T + 7) / 8, 256>>>(eouts, B * T, D);
    k_alpha<<<B, 256>>>(alpha_o, ylens, T, D);
    k_scan<<<B, 256>>>(alpha_o, aws, elens, ylens, T, L + 1);
    k_fired<<<dim3(L, B), 128>>>(eouts, aws, fired, T, D, L);
}

// round 3
// speedup vs baseline: 1.8040x; 1.8040x over previous
#include <cuda_runtime.h>
#include <math.h>

#define KHALF 5
#define KW 11
#define KWP 12          // padded row stride for d_g
#define MAXB 16
#define MAXT 2048
#define MAXD 512
#define MAXL 160
#define THRESH 0.9f

// ---- device scratch (no allocations allowed) ----
__device__ float d_weff[KW * MAXD + 4];            // folded conv*proj weights; bias at [KW*MAXD]
__device__ float d_g[MAXB * MAXT * KWP];           // per-(b,t) dot with each of 11 taps (padded)
__device__ float d_apart[MAXB * 16];               // per-(b,chunk) alpha partial sums
__device__ int   d_tfire[MAXB * MAXL];             // fire time of slot l for batch b
__device__ int   d_nfinal[MAXB];                   // number of fired tokens per batch

// ---------------------------------------------------------------------------
__global__ void k_memset0(float* p, int n) {
    int i = blockIdx.x * blockDim.x + threadIdx.x;
    int stride = gridDim.x * blockDim.x;
    int n4 = n >> 2;
    float4 z = make_float4(0.f, 0.f, 0.f, 0.f);
    float4* p4 = (float4*)p;
    for (int j = i; j < n4; j += stride) p4[j] = z;
    for (int j = n4 * 4 + i; j < n; j += stride) p[j] = 0.f;
}

// ---------------------------------------------------------------------------
// w_eff[k*D+d] = sum_c conv_w[(k*D+d)*C + c] * proj_w[c]; bias at slot KW*MAXD.
__global__ void k_weff(const float* __restrict__ cw, const float* __restrict__ cb,
                       const float* __restrict__ pw, const float* __restrict__ pb,
                       int D, int C) {
    int wid  = (blockIdx.x * blockDim.x + threadIdx.x) >> 5;
    int lane = threadIdx.x & 31;
    int NE = KW * D;
    if (wid > NE) return;
    float s = 0.f;
    if (wid == NE) {
        for (int c = lane; c < C; c += 32) s += cb[c] * pw[c];
    } else {
        const float* row = cw + (size_t)wid * C;
        for (int c = lane; c < C; c += 32) s += row[c] * pw[c];
    }
#pragma unroll
    for (int o = 16; o > 0; o >>= 1) s += __shfl_xor_sync(0xffffffffu, s, o);
    if (lane == 0) {
        if (wid == NE) d_weff[KW * MAXD] = s + pb[0];
        else           d_weff[wid] = s;
    }
}

// ---------------------------------------------------------------------------
// g[row*KWP + k] = dot(eouts[row,:], w_eff[k,:]); warp handles 4 rows, D==512.
__global__ void __launch_bounds__(256) k_g(const float* __restrict__ e, int BT) {
    __shared__ float4 sw[KW * 128];     // 11 * 512 floats = 22.5 KB
    {
        const float4* w4g = (const float4*)d_weff;
        for (int i = threadIdx.x; i < KW * 128; i += 256) sw[i] = w4g[i];
    }
    __syncthreads();
    int warp = blockIdx.x * 8 + (threadIdx.x >> 5);
    int lane = threadIdx.x & 31;
    int row0 = warp * 4;
    if (row0 >= BT) return;

    const float4* e4 = (const float4*)e;
    float4 ev[4][4];
#pragma unroll
    for (int r = 0; r < 4; r++)
#pragma unroll
        for (int jj = 0; jj < 4; jj++)
            ev[r][jj] = e4[(size_t)(row0 + r) * 128 + jj * 32 + lane];

    float acc[KW][4];
#pragma unroll
    for (int k = 0; k < KW; k++)
#pragma unroll
        for (int r = 0; r < 4; r++) acc[k][r] = 0.f;

#pragma unroll
    for (int k = 0; k < KW; k++) {
#pragma unroll
        for (int jj = 0; jj < 4; jj++) {
            float4 w4 = sw[k * 128 + jj * 32 + lane];
#pragma unroll
            for (int r = 0; r < 4; r++) {
                acc[k][r] += ev[r][jj].x * w4.x;
                acc[k][r] += ev[r][jj].y * w4.y;
                acc[k][r] += ev[r][jj].z * w4.z;
                acc[k][r] += ev[r][jj].w * w4.w;
            }
        }
    }
#pragma unroll
    for (int k = 0; k < KW; k++)
#pragma unroll
        for (int r = 0; r < 4; r++) {
            float v = acc[k][r];
#pragma unroll
            for (int o = 16; o > 0; o >>= 1) v += __shfl_xor_sync(0xffffffffu, v, o);
            acc[k][r] = v;
        }
    if (lane == 0) {
#pragma unroll
        for (int r = 0; r < 4; r++) {
            float4* gr = (float4*)(d_g + (size_t)(row0 + r) * KWP);
            gr[0] = make_float4(acc[0][r], acc[1][r], acc[2][r],  acc[3][r]);
            gr[1] = make_float4(acc[4][r], acc[5][r], acc[6][r],  acc[7][r]);
            gr[2] = make_float4(acc[8][r], acc[9][r], acc[10][r], 0.f);
        }
    }
}

// ---------------------------------------------------------------------------
// alpha[b,t] = sigmoid(band-sum of g + bias); per-chunk deterministic partials.
__global__ void k_alpha(float* __restrict__ alpha_out, int T) {
    __shared__ float red[256];
    int b = blockIdx.y;
    int t = blockIdx.x * 256 + threadIdx.x;
    float a = 0.f;
    if (t < T) {
        const float* gb = d_g + (size_t)b * T * KWP;
        float x = d_weff[KW * MAXD];
#pragma unroll
        for (int k = 0; k < KW; k++) {
            int tt = t + k - KHALF;
            if (tt >= 0 && tt < T) x += gb[tt * KWP + k];
        }
        a = 1.0f / (1.0f + expf(-x));
        alpha_out[(size_t)b * T + t] = a;
    }
    red[threadIdx.x] = a;
    __syncthreads();
    for (int s = 128; s > 0; s >>= 1) {
        if (threadIdx.x < s) red[threadIdx.x] += red[threadIdx.x + s];
        __syncthreads();
    }
    if (threadIdx.x == 0) d_apart[b * 16 + blockIdx.x] = red[0];
}

// ---------------------------------------------------------------------------
// Integrate-and-fire. Phase 1: minimal branchless serial recurrence producing
// the s_t trace. Phase 2: fully parallel reconstruction of fires / slots /
// weights via ballot + prefix popcount, writing aws directly.
__global__ void k_scan(const float* __restrict__ alpha_out, float* __restrict__ aws,
                       const int* __restrict__ elens, const int* __restrict__ ylens,
                       int T, int Lp1, int nch) {
    __shared__ float sa[MAXT];
    __shared__ float ss[MAXT];
    __shared__ unsigned sword[MAXT / 32];
    __shared__ int scnt[MAXT / 32];
    __shared__ float s_sum;

    int b = blockIdx.x;
    int tid = threadIdx.x;
    int el = elens[b], yl = ylens[b];

    if (tid == 0) {
        float sum = 0.f;
        for (int c = 0; c < nch; c++) sum += d_apart[b * 16 + c];
        s_sum = sum;
    }
    __syncthreads();
    float sum = s_sum;
    float yf = (float)yl;
    for (int t = tid; t < T; t += 256)
        sa[t] = (alpha_out[(size_t)b * T + t] / sum) * yf;   // match ref: (alpha/sum)*yl
    __syncthreads();

    // ---- phase 1: serial s-trace (yl-cap deliberately omitted; suppressed in phase 2)
    if (tid == 0) {
        float acc = 0.f;
        int t = 0;
#define CIF_STEP(tt) { float a_ = sa[tt]; float s_ = acc + a_; ss[tt] = s_; \
                       acc = (s_ >= THRESH) ? (s_ + (a_ - 1.0f)) : s_; }
        for (; t + 8 <= el; t += 8) {
            CIF_STEP(t);     CIF_STEP(t + 1); CIF_STEP(t + 2); CIF_STEP(t + 3);
            CIF_STEP(t + 4); CIF_STEP(t + 5); CIF_STEP(t + 6); CIF_STEP(t + 7);
        }
        for (; t < el; t++) CIF_STEP(t);
#undef CIF_STEP
    }
    __syncthreads();

    // ---- phase 2a: candidate ballots (t uniform stride, T % 256 == 0)
    for (int t = tid; t < T; t += 256) {
        bool cand = (t < el) && (ss[t] >= THRESH);
        unsigned bal = __ballot_sync(0xffffffffu, cand);
        if ((t & 31) == 0) { sword[t >> 5] = bal; scnt[t >> 5] = __popc(bal); }
    }
    __syncthreads();
    // ---- phase 2b: exclusive prefix over words
    if (tid == 0) {
        int run = 0, nw = T >> 5;
        for (int w = 0; w < nw; w++) { int c = scnt[w]; scnt[w] = run; run += c; }
        d_nfinal[b] = run < yl ? run : yl;
    }
    __syncthreads();
    // ---- phase 2c: reconstruct weights, write aws + fire times
    float* awb = aws + (size_t)b * Lp1 * T;
    for (int t = tid; t < T; t += 256) {
        if (t >= el) continue;
        float s = ss[t];
        float a = sa[t];
        unsigned w = sword[t >> 5];
        int rank = scnt[t >> 5] + __popc(w & ((1u << (t & 31)) - 1u));
        if (rank >= yl) continue;                 // inactive (token cap reached)
        bool fire = (s >= THRESH);
        float wold = fire ? (1.0f - s) : a;
        awb[(size_t)rank * T + t] = wold;
        if (fire) {
            awb[(size_t)(rank + 1) * T + t] = s + (a - 1.0f);
            d_tfire[b * MAXL + rank] = t;
        }
    }
}

// ---------------------------------------------------------------------------
// fired[b,l,:] = sum_{t=tlo..thi} aws[b,l,t] * eouts[b,t,:]
__global__ void k_fired(const float* __restrict__ e, const float* __restrict__ aws,
                        float* __restrict__ fired, int T, int D, int L) {
    int b = blockIdx.y, l = blockIdx.x;
    if (l >= d_nfinal[b]) return;
    int tlo = (l == 0) ? 0 : d_tfire[b * MAXL + l - 1];
    int thi = d_tfire[b * MAXL + l];
    const float* awr = aws + ((size_t)b * (L + 1) + l) * T;
    const float4* eb = (const float4*)(e + (size_t)b * T * D);
    int d4 = threadIdx.x;                        // 128 threads cover D=512 as float4
    float4 acc = make_float4(0.f, 0.f, 0.f, 0.f);
    for (int t = tlo; t <= thi; t++) {
        float w = awr[t];
        float4 ev = eb[(size_t)t * (D / 4) + d4];
        acc.x += w * ev.x; acc.y += w * ev.y;
        acc.z += w * ev.z; acc.w += w * ev.w;
    }
    ((float4*)(fired + ((size_t)b * L + l) * D))[d4] = acc;
}

// ---------------------------------------------------------------------------
extern "C" void kernel_launch(void* const* d_in, const int* in_sizes, int n_in,
                              void* d_out, int out_size) {
    const float* eouts  = (const float*)d_in[0];
    const float* conv_w = (const float*)d_in[1];
    const float* conv_b = (const float*)d_in[2];
    const float* proj_w = (const float*)d_in[3];
    const float* proj_b = (const float*)d_in[4];
    const int*   elens  = (const int*)d_in[5];
    const int*   ylens  = (const int*)d_in[6];

    int B = in_sizes[5];
    int C = in_sizes[2];
    int D = in_sizes[1] / (KW * C);
    int T = in_sizes[0] / (B * D);
    int L = (out_size - 2 * B * T) / (B * (D + T));

    float* fired   = (float*)d_out;
    float* alpha_o = fired + (size_t)B * L * D;
    float* aws     = alpha_o + (size_t)B * T;

    int BT = B * T;
    int nch = (T + 255) / 256;

    k_memset0<<<1024, 256>>>((float*)d_out, out_size);
    k_weff<<<(KW * D + 1 + 7) / 8, 256>>>(conv_w, conv_b, proj_w, proj_b, D, C);
    k_g<<<(BT / 4 + 7) / 8, 256>>>(eouts, BT);
    k_alpha<<<dim3(nch, B), 256>>>(alpha_o, T);
    k_scan<<<B, 256>>>(alpha_o, aws, elens, ylens, T, L + 1, nch);
    k_fired<<<dim3(L, B), 128>>>(eouts, aws, fired, T, D, L);
}